// round 1
// baseline (speedup 1.0000x reference)
#include <cuda_runtime.h>
#include <cstdint>

#define NN   50000
#define DEG  16
#define FD   160          // F = IN_CH + TYPE_DIM
#define HD   160          // hidden
#define GD   640          // 4*H gates
#define KD   320          // F + H (concat GEMM K)
#define OC   128          // output channels

#define TM   64           // nodes per CTA
#define NT   512          // threads per CTA
#define KC   16           // K-chunk staged in smem
#define NCHUNK (KD/KC)    // 20

// -------- device scratch (static allocations are the sanctioned scratch path) ----
__device__ float g_hin[NN * FD];          // concat(x, emb[type])  (32 MB, L2-resident)
__device__ float g_Wpack[KD * HD * 4];    // [k][m][{i,f,g,o}] gate-interleaved
__device__ float g_bias[GD];              // b_ih + b_hh
__device__ float g_Wfin[KD * OC];         // [k][j]; k<160 -> W_r, k>=160 -> W_l

// -------- small helpers -----------------------------------------------------------
__device__ __forceinline__ unsigned long long lds64(uint32_t addr) {
    unsigned long long v;
    asm("ld.shared.b64 %0, [%1];" : "=l"(v) : "r"(addr));
    return v;
}
__device__ __forceinline__ void fma2(unsigned long long& d, unsigned long long a,
                                     unsigned long long b) {
    asm("fma.rn.f32x2 %0, %1, %2, %0;" : "+l"(d) : "l"(a), "l"(b));
}
__device__ __forceinline__ unsigned long long pack2(float lo, float hi) {
    unsigned long long v;
    asm("mov.b64 %0, {%1, %2};" : "=l"(v) : "f"(lo), "f"(hi));
    return v;
}
__device__ __forceinline__ void unpack2(unsigned long long v, float& lo, float& hi) {
    asm("mov.b64 {%0, %1}, %2;" : "=f"(lo), "=f"(hi) : "l"(v));
}
__device__ __forceinline__ float sigm(float x) { return 1.f / (1.f + __expf(-x)); }

// -------- prep kernels ------------------------------------------------------------
__global__ void prep_hin(const float* __restrict__ x, const int* __restrict__ tids,
                         const float* __restrict__ emb) {
    int i = blockIdx.x * blockDim.x + threadIdx.x;
    if (i >= NN * FD) return;
    int n = i / FD, c = i % FD;
    g_hin[i] = (c < 128) ? x[n * 128 + c] : emb[tids[n] * 32 + (c - 128)];
}

__global__ void prep_w(const float* __restrict__ Wih, const float* __restrict__ Whh,
                       const float* __restrict__ bih, const float* __restrict__ bhh,
                       const float* __restrict__ Wl,  const float* __restrict__ Wr) {
    int i = blockIdx.x * blockDim.x + threadIdx.x;
    if (i < KD * HD * 4) {
        int g = i & 3;
        int m = (i >> 2) % HD;
        int k = (i >> 2) / HD;
        int j = g * HD + m;                       // gate row in [640]
        g_Wpack[i] = (k < FD) ? Wih[j * FD + k] : Whh[j * HD + (k - FD)];
    }
    if (i < GD) g_bias[i] = bih[i] + bhh[i];
    if (i < KD * OC) {
        int k = i / OC, j = i % OC;
        g_Wfin[i] = (k < HD) ? Wr[j * FD + k] : Wl[j * FD + (k - HD)];
    }
}

// -------- main fused kernel -------------------------------------------------------
// smem: As[TM][KD] (x_t | h), Ws[KC][GD] weight chunk, biasS[GD] packed, srcS[TM]
#define SMEM_FLOATS (TM * KD + KC * GD + GD)
#define SMEM_BYTES  (SMEM_FLOATS * 4 + TM * 4)

__global__ void __launch_bounds__(NT, 1)
lstm_main(const int* __restrict__ esrc, const float* __restrict__ bl,
          float* __restrict__ out) {
    extern __shared__ float sm[];
    float* As    = sm;                    // [TM][KD]
    float* Ws    = sm + TM * KD;          // [KC][GD]
    float* biasS = Ws + KC * GD;          // [GD] packed [m][4]
    int*   srcS  = (int*)(biasS + GD);    // [TM]

    const int tid = threadIdx.x;
    const int c   = tid & 31;             // lane = gate-col group
    const int rg  = tid >> 5;             // warp = row group
    const int r0  = rg * 4;
    const int nodeBase = blockIdx.x * TM;

    uint32_t sbase;
    asm("{ .reg .u64 t; cvta.to.shared.u64 t, %1; cvt.u32.u64 %0, t; }"
        : "=r"(sbase) : "l"(sm));
    const uint32_t WsB = sbase + (uint32_t)(TM * KD) * 4u;

    // bias -> packed smem layout [m][{i,f,g,o}]
    for (int i = tid; i < GD; i += NT) {
        int m = i >> 2, g = i & 3;
        biasS[i] = g_bias[g * HD + m];
    }
    // zero h region (columns 160..319 of As)
    for (int i = tid; i < TM * HD; i += NT) {
        int r = i / HD, col = i % HD;
        As[r * KD + FD + col] = 0.f;
    }

    unsigned long long accIF[4][5], accGO[4][5];
    float cst[4][5];
#pragma unroll
    for (int i = 0; i < 4; i++)
#pragma unroll
        for (int n = 0; n < 5; n++) { accIF[i][n] = 0ull; accGO[i][n] = 0ull; cst[i][n] = 0.f; }

    for (int t = 0; t < DEG; t++) {
        // ---- neighbor indices for this timestep (dst is sorted: edge e = node*16 + t)
        if (tid < TM) {
            int node = nodeBase + tid;
            if (node >= NN) node = NN - 1;
            srcS[tid] = esrc[node * DEG + t];
        }
        __syncthreads();
        // ---- gather x_t = h_in[src] into As[:, 0:160]
        for (int i = tid; i < TM * FD; i += NT) {
            int r = i / FD, col = i % FD;
            As[r * KD + col] = g_hin[srcS[r] * FD + col];
        }
        __syncthreads();

        // ---- gates = [x_t | h] @ Wcat  (K=320, N=640), K-chunked through smem
        for (int ch = 0; ch < NCHUNK; ch++) {
            const float4* s4 = (const float4*)(g_Wpack + ch * (KC * GD));
            float4* d4 = (float4*)Ws;
#pragma unroll
            for (int u = 0; u < (KC * GD / 4) / NT; u++)   // 5 float4 per thread
                d4[tid + u * NT] = s4[tid + u * NT];
            __syncthreads();
#pragma unroll
            for (int kk = 0; kk < KC; kk++) {
                const int k = ch * KC + kk;
                unsigned long long a2[4];
#pragma unroll
                for (int i = 0; i < 4; i++) {
                    float a = As[(r0 + i) * KD + k];       // warp-broadcast LDS
                    a2[i] = pack2(a, a);
                }
#pragma unroll
                for (int n = 0; n < 5; n++) {
                    uint32_t wa = WsB + (uint32_t)(kk * GD + (c * 5 + n) * 4) * 4u;
                    unsigned long long wif = lds64(wa);      // (W_i, W_f)
                    unsigned long long wgo = lds64(wa + 8);  // (W_g, W_o)
#pragma unroll
                    for (int i = 0; i < 4; i++) {
                        fma2(accIF[i][n], a2[i], wif);
                        fma2(accGO[i][n], a2[i], wgo);
                    }
                }
            }
            __syncthreads();
        }

        // ---- LSTM cell update (c in registers), write h back into As[:,160:320]
#pragma unroll
        for (int n = 0; n < 5; n++) {
            const int m = c * 5 + n;
            float4 bb = *(float4*)&biasS[m * 4];
#pragma unroll
            for (int i = 0; i < 4; i++) {
                float gi, gf, gg, go;
                unpack2(accIF[i][n], gi, gf);
                unpack2(accGO[i][n], gg, go);
                gi += bb.x; gf += bb.y; gg += bb.z; go += bb.w;
                float iv = sigm(gi), fv = sigm(gf), ov = sigm(go);
                float gv = tanhf(gg);
                float cv = fv * cst[i][n] + iv * gv;
                cst[i][n] = cv;
                As[(r0 + i) * KD + FD + m] = ov * tanhf(cv);
                accIF[i][n] = 0ull; accGO[i][n] = 0ull;
            }
        }
        // next iteration's first __syncthreads() orders these writes before reads
    }

    // ---- final layer: out = relu([h_in_node | h_last] @ Wfin + b_l)
    for (int i = tid; i < TM * FD; i += NT) {
        int r = i / FD, col = i % FD;
        int node = nodeBase + r;
        if (node >= NN) node = NN - 1;
        As[r * KD + col] = g_hin[node * FD + col];
    }
    __syncthreads();

    unsigned long long a01[4], a23[4];
#pragma unroll
    for (int i = 0; i < 4; i++) { a01[i] = 0ull; a23[i] = 0ull; }

    for (int ch = 0; ch < NCHUNK; ch++) {
        ((float4*)Ws)[tid] = ((const float4*)(g_Wfin))[ch * (KC * OC / 4) + tid];
        __syncthreads();
#pragma unroll
        for (int kk = 0; kk < KC; kk++) {
            const int k = ch * KC + kk;
            unsigned long long a2[4];
#pragma unroll
            for (int i = 0; i < 4; i++) {
                float a = As[(r0 + i) * KD + k];
                a2[i] = pack2(a, a);
            }
            uint32_t wa = WsB + (uint32_t)(kk * OC + c * 4) * 4u;
            unsigned long long w01 = lds64(wa);
            unsigned long long w23 = lds64(wa + 8);
#pragma unroll
            for (int i = 0; i < 4; i++) {
                fma2(a01[i], a2[i], w01);
                fma2(a23[i], a2[i], w23);
            }
        }
        __syncthreads();
    }

    float4 blv = *(const float4*)(bl + c * 4);
#pragma unroll
    for (int i = 0; i < 4; i++) {
        int node = nodeBase + r0 + i;
        float o0, o1, o2, o3;
        unpack2(a01[i], o0, o1);
        unpack2(a23[i], o2, o3);
        o0 = fmaxf(o0 + blv.x, 0.f);
        o1 = fmaxf(o1 + blv.y, 0.f);
        o2 = fmaxf(o2 + blv.z, 0.f);
        o3 = fmaxf(o3 + blv.w, 0.f);
        if (node < NN)
            *(float4*)(out + node * OC + c * 4) = make_float4(o0, o1, o2, o3);
    }
}

// -------- launch ------------------------------------------------------------------
extern "C" void kernel_launch(void* const* d_in, const int* in_sizes, int n_in,
                              void* d_out, int out_size) {
    const float* x    = (const float*)d_in[0];
    const int*   tids = (const int*)  d_in[1];
    const int*   eidx = (const int*)  d_in[2];   // [2][E]; row 0 = src
    const float* emb  = (const float*)d_in[3];
    const float* Wih  = (const float*)d_in[4];
    const float* Whh  = (const float*)d_in[5];
    const float* bih  = (const float*)d_in[6];
    const float* bhh  = (const float*)d_in[7];
    const float* Wl   = (const float*)d_in[8];
    const float* bl   = (const float*)d_in[9];
    const float* Wr   = (const float*)d_in[10];
    float* out = (float*)d_out;

    prep_hin<<<(NN * FD + 255) / 256, 256>>>(x, tids, emb);
    prep_w<<<(KD * HD * 4 + 255) / 256, 256>>>(Wih, Whh, bih, bhh, Wl, Wr);

    cudaFuncSetAttribute(lstm_main, cudaFuncAttributeMaxDynamicSharedMemorySize,
                         SMEM_BYTES);
    lstm_main<<<(NN + TM - 1) / TM, NT, SMEM_BYTES>>>(eidx, bl, out);
}

// round 4
// speedup vs baseline: 2.1443x; 2.1443x over previous
#include <cuda_runtime.h>
#include <cstdint>

#define NN   50000
#define DEG  16
#define FD   160
#define HD   160
#define GD   640          // 4*H
#define OC   128
#define KHH  160          // K of recurrence GEMM

#define TM   64           // nodes per CTA
#define NT   256          // threads
#define NW   8            // warps
#define RPT  8            // rows per warp
#define KC   16
#define NCH  (KHH/KC)     // 10
#define CHF  (KC*GD)      // floats per chunk = 10240
#define CHB  (CHF*4)      // bytes per chunk  = 40960

// ---------------- device scratch ----------------
__device__ float g_hin[NN * FD];
__device__ float g_WihP[KHH * HD * 4];   // [k][m][{i,f,g,o}]
__device__ float g_WhhP[KHH * HD * 4];   // [k][m][{i,f,g,o}]
__device__ float g_bias[GD];             // packed [m][g], b_ih+b_hh
__device__ float g_WlP[KHH * OC];        // [k][j]
__device__ float g_WrP[KHH * OC];        // [k][j]
__device__ float g_P[NN * GD];           // 128 MB: x@Wih + biases
__device__ float g_Q[NN * OC];           // hin@Wr + b_l

// ---------------- helpers ----------------
typedef unsigned long long ull;

__device__ __forceinline__ ull pack2(float lo, float hi) {
    ull v; asm("mov.b64 %0, {%1, %2};" : "=l"(v) : "f"(lo), "f"(hi)); return v;
}
__device__ __forceinline__ void unpack2(ull v, float& lo, float& hi) {
    asm("mov.b64 {%0, %1}, %2;" : "=f"(lo), "=f"(hi) : "l"(v));
}
__device__ __forceinline__ void fma2(ull& d, ull a, ull b) {
    asm("fma.rn.f32x2 %0, %1, %2, %0;" : "+l"(d) : "l"(a), "l"(b));
}
__device__ __forceinline__ void ldsv2(uint32_t a, ull& x, ull& y) {
    asm("ld.shared.v2.u64 {%0,%1}, [%2];" : "=l"(x), "=l"(y) : "r"(a));
}
__device__ __forceinline__ void cp16(uint32_t s, const void* g) {
    asm volatile("cp.async.ca.shared.global [%0], [%1], 16;" :: "r"(s), "l"(g));
}
__device__ __forceinline__ void cpcommit() { asm volatile("cp.async.commit_group;"); }
template<int N> __device__ __forceinline__ void cpwait() {
    asm volatile("cp.async.wait_group %0;" :: "n"(N));
}
__device__ __forceinline__ float sigm(float x) {
    return __fdividef(1.f, 1.f + __expf(-x));
}
__device__ __forceinline__ float tanhfast(float x) {
    return __fdividef(2.f, 1.f + __expf(-2.f * x)) - 1.f;
}

__device__ __forceinline__ void stage_chunk(const float* gsrc, uint32_t sdst, int tid) {
#pragma unroll
    for (int u = 0; u < 10; u++)
        cp16(sdst + (uint32_t)(tid * 16 + u * 4096), gsrc + tid * 4 + u * 1024);
    cpcommit();
}

// K=160 GEMM: acc[8 rows][5 n] over gate pairs, weights streamed via cp.async
__device__ __forceinline__ void gemm160(const float* __restrict__ gW, uint32_t wsbase,
                                        const float* __restrict__ hrow, int tid, int c,
                                        ull accIF[RPT][5], ull accGO[RPT][5]) {
    stage_chunk(gW, wsbase, tid);
    stage_chunk(gW + CHF, wsbase + CHB, tid);
    for (int ch = 0; ch < NCH; ch++) {
        if (ch == NCH - 1) cpwait<0>(); else cpwait<1>();
        __syncthreads();
        const uint32_t wb0 = wsbase + (uint32_t)(ch & 1) * CHB;
#pragma unroll
        for (int kk = 0; kk < KC; kk++) {
            ull a2[RPT];
#pragma unroll
            for (int i = 0; i < RPT; i++) {
                float a = hrow[i * KHH + ch * KC + kk];   // warp-broadcast LDS
                a2[i] = pack2(a, a);
            }
            const uint32_t wb = wb0 + (uint32_t)(kk * 2560 + c * 16);
#pragma unroll
            for (int n = 0; n < 5; n++) {
                ull wif, wgo;
                ldsv2(wb + (uint32_t)(n * 512), wif, wgo);
#pragma unroll
                for (int i = 0; i < RPT; i++) {
                    fma2(accIF[i][n], a2[i], wif);
                    fma2(accGO[i][n], a2[i], wgo);
                }
            }
        }
        __syncthreads();
        if (ch < NCH - 2) stage_chunk(gW + (ch + 2) * CHF, wsbase + (uint32_t)(ch & 1) * CHB, tid);
    }
}

// ---------------- prep kernels ----------------
__global__ void prep_hin(const float* __restrict__ x, const int* __restrict__ tids,
                         const float* __restrict__ emb) {
    int i = blockIdx.x * blockDim.x + threadIdx.x;
    if (i >= NN * FD) return;
    int n = i / FD, c = i % FD;
    g_hin[i] = (c < 128) ? x[n * 128 + c] : emb[tids[n] * 32 + (c - 128)];
}

__global__ void prep_w(const float* __restrict__ Wih, const float* __restrict__ Whh,
                       const float* __restrict__ bih, const float* __restrict__ bhh,
                       const float* __restrict__ Wl,  const float* __restrict__ Wr) {
    int i = blockIdx.x * blockDim.x + threadIdx.x;
    if (i < KHH * HD * 4) {
        int g = i & 3, m = (i >> 2) % HD, k = (i >> 2) / HD;
        int j = g * HD + m;
        g_WihP[i] = Wih[j * FD + k];
        g_WhhP[i] = Whh[j * HD + k];
    }
    if (i < GD) {
        int m = i >> 2, g = i & 3;
        g_bias[i] = bih[g * HD + m] + bhh[g * HD + m];
    }
    if (i < KHH * OC) {
        int k = i / OC, j = i % OC;
        g_WlP[i] = Wl[j * FD + k];
        g_WrP[i] = Wr[j * FD + k];
    }
}

// P = hin@Wih^T + b ; Q = hin@Wr^T + b_l
__global__ void __launch_bounds__(NT, 1)
prep_PQ(const float* __restrict__ bl) {
    extern __shared__ float sm[];
    float* hs = sm;                       // [64][160]
    const uint32_t sbase = (uint32_t)__cvta_generic_to_shared(sm);
    const uint32_t wsbase = sbase + TM * KHH * 4;   // Ws double buffer

    const int tid = threadIdx.x, c = tid & 31, warp = tid >> 5;
    const int nodeBase = blockIdx.x * TM;
    float* hrow = hs + warp * RPT * KHH;

    // load hin rows (clamped)
#pragma unroll
    for (int u = 0; u < 10; u++) {
        int idx4 = tid + u * NT;                  // float4 units, 2560 total
        int r = idx4 / 40, col4 = idx4 % 40;
        int node = nodeBase + r; if (node >= NN) node = NN - 1;
        ((float4*)hs)[idx4] = ((const float4*)g_hin)[node * 40 + col4];
    }
    __syncthreads();

    ull accIF[RPT][5], accGO[RPT][5];
#pragma unroll
    for (int n = 0; n < 5; n++) {
        float4 b = ((const float4*)g_bias)[n * 32 + c];
#pragma unroll
        for (int i = 0; i < RPT; i++) {
            accIF[i][n] = pack2(b.x, b.y);
            accGO[i][n] = pack2(b.z, b.w);
        }
    }
    gemm160(g_WihP, wsbase, hrow, tid, c, accIF, accGO);

#pragma unroll
    for (int i = 0; i < RPT; i++) {
        int node = nodeBase + warp * RPT + i;
        if (node < NN) {
#pragma unroll
            for (int n = 0; n < 5; n++) {
                float4 o;
                unpack2(accIF[i][n], o.x, o.y);
                unpack2(accGO[i][n], o.z, o.w);
                ((float4*)g_P)[node * 160 + n * 32 + c] = o;
            }
        }
    }

    // ---- Q phase: stage full Wr (20480 floats = both Ws buffers)
    __syncthreads();
    float* Wfs = hs + TM * KHH;
    for (int u = tid; u < KHH * OC / 4; u += NT)
        ((float4*)Wfs)[u] = ((const float4*)g_WrP)[u];
    __syncthreads();

    float4 q[RPT];
    float4 blv = ((const float4*)bl)[c];
#pragma unroll
    for (int i = 0; i < RPT; i++) q[i] = blv;
    for (int k = 0; k < KHH; k++) {
        float4 w = ((const float4*)Wfs)[k * 32 + c];
#pragma unroll
        for (int i = 0; i < RPT; i++) {
            float a = hrow[i * KHH + k];
            q[i].x = fmaf(a, w.x, q[i].x);
            q[i].y = fmaf(a, w.y, q[i].y);
            q[i].z = fmaf(a, w.z, q[i].z);
            q[i].w = fmaf(a, w.w, q[i].w);
        }
    }
#pragma unroll
    for (int i = 0; i < RPT; i++) {
        int node = nodeBase + warp * RPT + i;
        if (node < NN) ((float4*)g_Q)[node * 32 + c] = q[i];
    }
}

// ---------------- main recurrence kernel ----------------
// smem: hs[64*160] | Ws[2][10240] | cst[40*256] | src[64]
#define SM_MAIN (TM*KHH*4 + 2*CHB + 40*NT*4 + TM*4)

__global__ void __launch_bounds__(NT, 1)
lstm_main(const int* __restrict__ esrc, float* __restrict__ out) {
    extern __shared__ float sm[];
    float* hs   = sm;
    float* cstS = sm + TM * KHH + 2 * CHF;
    int*   srcS = (int*)(cstS + 40 * NT);
    const uint32_t sbase  = (uint32_t)__cvta_generic_to_shared(sm);
    const uint32_t wsbase = sbase + TM * KHH * 4;

    const int tid = threadIdx.x, c = tid & 31, warp = tid >> 5;
    const int nodeBase = blockIdx.x * TM;
    float* hrow = hs + warp * RPT * KHH;

    // init h = 0 (warp-private rows), c-state = 0 (thread-private slots)
    for (int u = c; u < RPT * KHH; u += 32) hrow[u] = 0.f;
#pragma unroll
    for (int j = 0; j < 40; j++) cstS[j * NT + tid] = 0.f;
    __syncwarp();

    ull accIF[RPT][5], accGO[RPT][5];
    const float4* P4 = (const float4*)g_P;

    for (int t = 0; t < DEG; t++) {
        if (tid < TM) {
            int node = nodeBase + tid; if (node >= NN) node = NN - 1;
            srcS[tid] = esrc[node * DEG + t];
        }
        __syncthreads();

        // acc init = gather P[src]  (coalesced float4, lane-stride 16B)
#pragma unroll
        for (int i = 0; i < RPT; i++) {
            int s = srcS[warp * RPT + i];
#pragma unroll
            for (int n = 0; n < 5; n++) {
                float4 p = P4[s * 160 + n * 32 + c];
                accIF[i][n] = pack2(p.x, p.y);
                accGO[i][n] = pack2(p.z, p.w);
            }
        }

        gemm160(g_WhhP, wsbase, hrow, tid, c, accIF, accGO);

        // LSTM cell update; h rows are warp-private -> __syncwarp only
#pragma unroll
        for (int i = 0; i < RPT; i++) {
#pragma unroll
            for (int n = 0; n < 5; n++) {
                float gi, gf, gg, go;
                unpack2(accIF[i][n], gi, gf);
                unpack2(accGO[i][n], gg, go);
                float iv = sigm(gi), fv = sigm(gf), ov = sigm(go);
                float gv = tanhfast(gg);
                int j = i * 5 + n;
                float cv = fv * cstS[j * NT + tid] + iv * gv;
                cstS[j * NT + tid] = cv;
                hrow[i * KHH + n * 32 + c] = ov * tanhfast(cv);
            }
        }
        __syncwarp();
    }

    // ---- final layer: out = relu(Q[node] + h @ Wl^T)
    __syncthreads();
    float* Wfs = hs + TM * KHH;             // reuse both Ws buffers (80 KB)
    for (int u = tid; u < KHH * OC / 4; u += NT)
        ((float4*)Wfs)[u] = ((const float4*)g_WlP)[u];
    __syncthreads();

    float4 q[RPT];
#pragma unroll
    for (int i = 0; i < RPT; i++) {
        int nc = nodeBase + warp * RPT + i; if (nc >= NN) nc = NN - 1;
        q[i] = ((const float4*)g_Q)[nc * 32 + c];
    }
    for (int k = 0; k < KHH; k++) {
        float4 w = ((const float4*)Wfs)[k * 32 + c];
#pragma unroll
        for (int i = 0; i < RPT; i++) {
            float a = hrow[i * KHH + k];
            q[i].x = fmaf(a, w.x, q[i].x);
            q[i].y = fmaf(a, w.y, q[i].y);
            q[i].z = fmaf(a, w.z, q[i].z);
            q[i].w = fmaf(a, w.w, q[i].w);
        }
    }
#pragma unroll
    for (int i = 0; i < RPT; i++) {
        int node = nodeBase + warp * RPT + i;
        if (node < NN) {
            float4 o;
            o.x = fmaxf(q[i].x, 0.f); o.y = fmaxf(q[i].y, 0.f);
            o.z = fmaxf(q[i].z, 0.f); o.w = fmaxf(q[i].w, 0.f);
            ((float4*)out)[node * 32 + c] = o;
        }
    }
}

// ---------------- launch ----------------
extern "C" void kernel_launch(void* const* d_in, const int* in_sizes, int n_in,
                              void* d_out, int out_size) {
    const float* x    = (const float*)d_in[0];
    const int*   tids = (const int*)  d_in[1];
    const int*   eidx = (const int*)  d_in[2];   // [2][E]; row 0 = src
    const float* emb  = (const float*)d_in[3];
    const float* Wih  = (const float*)d_in[4];
    const float* Whh  = (const float*)d_in[5];
    const float* bih  = (const float*)d_in[6];
    const float* bhh  = (const float*)d_in[7];
    const float* Wl   = (const float*)d_in[8];
    const float* bl   = (const float*)d_in[9];
    const float* Wr   = (const float*)d_in[10];
    float* out = (float*)d_out;

    static bool attr_done = false;
    if (!attr_done) {
        cudaFuncSetAttribute(prep_PQ, cudaFuncAttributeMaxDynamicSharedMemorySize,
                             TM * KHH * 4 + 2 * CHB);
        cudaFuncSetAttribute(lstm_main, cudaFuncAttributeMaxDynamicSharedMemorySize,
                             SM_MAIN);
        attr_done = true;
    }

    prep_hin<<<(NN * FD + 255) / 256, 256>>>(x, tids, emb);
    prep_w<<<(KHH * HD * 4 + 255) / 256, 256>>>(Wih, Whh, bih, bhh, Wl, Wr);
    prep_PQ<<<(NN + TM - 1) / TM, NT, TM * KHH * 4 + 2 * CHB>>>(bl);
    lstm_main<<<(NN + TM - 1) / TM, NT, SM_MAIN>>>(eidx, out);
}